// round 3
// baseline (speedup 1.0000x reference)
#include <cuda_runtime.h>
#include <math.h>

#define NPTS 2048
#define NB   16
#define CHUNKS 8
#define TPB  256
#define NBLK (NB * CHUNKS)

typedef unsigned long long ull;

__device__ float g_A[NB * 9];     // per-batch folded rotation A = Rp^T * Rg
__device__ float g_part[NBLK];    // per-block partial sums (no atomics -> deterministic)

// ---- packed f32x2 helpers (sm_103a) ----
__device__ __forceinline__ ull pk2(float a, float b) {
    ull r; asm("mov.b64 %0, {%1, %2};" : "=l"(r) : "f"(a), "f"(b)); return r;
}
__device__ __forceinline__ ull fma2(ull a, ull b, ull c) {
    ull d; asm("fma.rn.f32x2 %0, %1, %2, %3;" : "=l"(d) : "l"(a), "l"(b), "l"(c)); return d;
}
__device__ __forceinline__ void upk2(ull v, float& a, float& b) {
    asm("mov.b64 {%0, %1}, %2;" : "=f"(a), "=f"(b) : "l"(v));
}

__device__ __forceinline__ void quat2mat(const float q[4], float R[3][3]) {
    float w = q[0], x = q[1], y = q[2], z = q[3];
    R[0][0] = 1.f - 2.f * (y * y + z * z);
    R[0][1] = 2.f * (x * y - w * z);
    R[0][2] = 2.f * (x * z + w * y);
    R[1][0] = 2.f * (x * y + w * z);
    R[1][1] = 1.f - 2.f * (x * x + z * z);
    R[1][2] = 2.f * (y * z - w * x);
    R[2][0] = 2.f * (x * z - w * y);
    R[2][1] = 2.f * (y * z + w * x);
    R[2][2] = 1.f - 2.f * (x * x + y * y);
}

// Kernel 1: quaternion math. 1 block, 32 threads; lanes 0..15 each handle a batch.
__global__ void prep_kernel(const float* __restrict__ pq,
                            const float* __restrict__ gq,
                            float* __restrict__ out) {
    int lane = threadIdx.x;
    float cos_term = 0.f;
    if (lane < NB) {
        float p[4], g[4];
#pragma unroll
        for (int i = 0; i < 4; i++) { p[i] = pq[lane * 4 + i]; g[i] = gq[lane * 4 + i]; }
        float dot = 0.f, np2 = 0.f, ng2 = 0.f;
#pragma unroll
        for (int i = 0; i < 4; i++) {
            dot += p[i] * g[i]; np2 += p[i] * p[i]; ng2 += g[i] * g[i];
        }
        float np = sqrtf(np2), ng = sqrtf(ng2);
        cos_term = 1.f - dot / fmaxf(np * ng, 1e-8f);
        float ip = 1.f / fmaxf(np, 1e-8f);
        float ig = 1.f / fmaxf(ng, 1e-8f);
#pragma unroll
        for (int i = 0; i < 4; i++) { p[i] *= ip; g[i] *= ig; }
        float Rp[3][3], Rg[3][3];
        quat2mat(p, Rp);
        quat2mat(g, Rg);
        // A = Rp^T * Rg : A[i][j] = sum_k Rp[k][i] * Rg[k][j]
#pragma unroll
        for (int i = 0; i < 3; i++)
#pragma unroll
            for (int j = 0; j < 3; j++) {
                float a = 0.f;
#pragma unroll
                for (int k = 0; k < 3; k++) a += Rp[k][i] * Rg[k][j];
                g_A[lane * 9 + i * 3 + j] = a;
            }
    }
    // lanes >= 16 contribute 0; full-warp tree sum
#pragma unroll
    for (int o = 16; o > 0; o >>= 1) cos_term += __shfl_down_sync(0xFFFFFFFFu, cos_term, o);
    if (lane == 0) out[0] = cos_term * (1.f / (float)NB);
}

// Kernel 2: fused rotate + pairwise-min. grid = 16 batches * 8 m-chunks.
// Each thread owns one m-point, scans all 2048 n-points via packed f32x2.
__global__ __launch_bounds__(TPB) void pair_kernel(const float* __restrict__ points) {
    // smA[j] = (r0[2j], r0[2j+1], r1[2j], r1[2j+1])
    // smB[j] = (r2[2j], r2[2j+1], s [2j], s [2j+1])
    __shared__ float4 smA[NPTS / 2];
    __shared__ float4 smB[NPTS / 2];
    __shared__ float red[TPB / 32];

    const int b     = blockIdx.x >> 3;
    const int chunk = blockIdx.x & 7;
    const int tid   = threadIdx.x;
    const float* __restrict__ P = points + b * 3 * NPTS;

    float A00 = g_A[b * 9 + 0], A01 = g_A[b * 9 + 1], A02 = g_A[b * 9 + 2];
    float A10 = g_A[b * 9 + 3], A11 = g_A[b * 9 + 4], A12 = g_A[b * 9 + 5];
    float A20 = g_A[b * 9 + 6], A21 = g_A[b * 9 + 7], A22 = g_A[b * 9 + 8];

    // Build r/s tables (all blocks of a batch recompute; trivial cost).
#pragma unroll
    for (int it = 0; it < (NPTS / 2) / TPB; it++) {
        int j  = tid + it * TPB;
        int n0 = 2 * j, n1 = n0 + 1;
        float x0 = P[n0],            y0 = P[NPTS + n0],     z0 = P[2 * NPTS + n0];
        float x1 = P[n1],            y1 = P[NPTS + n1],     z1 = P[2 * NPTS + n1];
        float r0a = A00 * x0 + A01 * y0 + A02 * z0;
        float r1a = A10 * x0 + A11 * y0 + A12 * z0;
        float r2a = A20 * x0 + A21 * y0 + A22 * z0;
        float sa  = x0 * x0 + y0 * y0 + z0 * z0;
        float r0b = A00 * x1 + A01 * y1 + A02 * z1;
        float r1b = A10 * x1 + A11 * y1 + A12 * z1;
        float r2b = A20 * x1 + A21 * y1 + A22 * z1;
        float sb  = x1 * x1 + y1 * y1 + z1 * z1;
        smA[j] = make_float4(r0a, r0b, r1a, r1b);
        smB[j] = make_float4(r2a, r2b, sa, sb);
    }
    __syncthreads();

    const int m = chunk * TPB + tid;
    float x = P[m], y = P[NPTS + m], z = P[2 * NPTS + m];
    float sm_ = x * x + y * y + z * z;
    ull u0 = pk2(-2.f * x, -2.f * x);
    ull u1 = pk2(-2.f * y, -2.f * y);
    ull u2 = pk2(-2.f * z, -2.f * z);

    float mn0 = INFINITY, mn1 = INFINITY, mn2 = INFINITY, mn3 = INFINITY;

#pragma unroll 4
    for (int j = 0; j < NPTS / 2; j += 2) {
        {
            float4 a = smA[j];
            float4 q = smB[j];
            ull t = fma2(pk2(q.x, q.y), u2, pk2(q.z, q.w));  // s - 2*r2*z (packed 2 n's)
            t = fma2(pk2(a.z, a.w), u1, t);
            t = fma2(pk2(a.x, a.y), u0, t);
            float fa, fb; upk2(t, fa, fb);
            mn0 = fminf(mn0, fa);
            mn1 = fminf(mn1, fb);
        }
        {
            float4 a = smA[j + 1];
            float4 q = smB[j + 1];
            ull t = fma2(pk2(q.x, q.y), u2, pk2(q.z, q.w));
            t = fma2(pk2(a.z, a.w), u1, t);
            t = fma2(pk2(a.x, a.y), u0, t);
            float fa, fb; upk2(t, fa, fb);
            mn2 = fminf(mn2, fa);
            mn3 = fminf(mn3, fb);
        }
    }

    // min_l2[m] = s[m] + min_n (s[n] - 2 r_n . p_m)
    float v = sm_ + fminf(fminf(mn0, mn1), fminf(mn2, mn3));

    // deterministic block sum
#pragma unroll
    for (int o = 16; o > 0; o >>= 1) v += __shfl_down_sync(0xFFFFFFFFu, v, o);
    if ((tid & 31) == 0) red[tid >> 5] = v;
    __syncthreads();
    if (tid < (TPB / 32)) {
        v = red[tid];
#pragma unroll
        for (int o = (TPB / 64); o > 0; o >>= 1) v += __shfl_down_sync(0xFFu, v, o);
        if (tid == 0) g_part[blockIdx.x] = v;
    }
}

// Kernel 3: reduce 128 partials -> pt_loss (with NaN guard), write out[1].
__global__ void finish_kernel(float* __restrict__ out) {
    int tid = threadIdx.x;  // 128 threads
    __shared__ float red[4];
    float v = g_part[tid];
#pragma unroll
    for (int o = 16; o > 0; o >>= 1) v += __shfl_down_sync(0xFFFFFFFFu, v, o);
    if ((tid & 31) == 0) red[tid >> 5] = v;
    __syncthreads();
    if (tid == 0) {
        float s = red[0] + red[1] + red[2] + red[3];
        float pt = s * (1.f / ((float)NB * (float)NPTS));
        if (isnan(pt)) pt = 0.f;
        out[1] = pt;
    }
}

extern "C" void kernel_launch(void* const* d_in, const int* in_sizes, int n_in,
                              void* d_out, int out_size) {
    const float* pq  = (const float*)d_in[0];  // predquat (16,4)
    const float* gq  = (const float*)d_in[1];  // gtquat   (16,4)
    const float* pts = (const float*)d_in[2];  // points   (16,3,2048)
    float* out = (float*)d_out;                // [cos_loss, pt_loss]

    prep_kernel<<<1, 32>>>(pq, gq, out);
    pair_kernel<<<NBLK, TPB>>>(pts);
    finish_kernel<<<1, 128>>>(out);
}

// round 5
// speedup vs baseline: 2.0885x; 2.0885x over previous
#include <cuda_runtime.h>
#include <math.h>

#define NPTS   2048
#define NB     16
#define NCHUNK 8          // n-dimension split per batch
#define TPB    256
#define MB     8          // m-points per thread (TPB*MB = NPTS)
#define NBLK   (NB * NCHUNK)

typedef unsigned long long ull;

__device__ float    g_A[NB * 9];          // per-batch folded rotation A = Rp^T * Rg
__device__ unsigned g_min[NB * NPTS];     // per-(b,m) running min, order-preserving uint keys
__device__ float    g_ssum[NBLK];         // partial sums of |p|^2

// ---- packed f32x2 helpers (sm_103a) ----
__device__ __forceinline__ ull pk2(float a, float b) {
    ull r; asm("mov.b64 %0, {%1, %2};" : "=l"(r) : "f"(a), "f"(b)); return r;
}
__device__ __forceinline__ ull fma2(ull a, ull b, ull c) {
    ull d; asm("fma.rn.f32x2 %0, %1, %2, %3;" : "=l"(d) : "l"(a), "l"(b), "l"(c)); return d;
}
__device__ __forceinline__ void upk2(ull v, float& a, float& b) {
    asm("mov.b64 {%0, %1}, %2;" : "=f"(a), "=f"(b) : "l"(v));
}

// ---- order-preserving float<->uint for atomicMin ----
__device__ __forceinline__ unsigned fenc(float f) {
    unsigned u = __float_as_uint(f);
    return (u & 0x80000000u) ? ~u : (u | 0x80000000u);
}
__device__ __forceinline__ float fdec(unsigned u) {
    unsigned v = (u & 0x80000000u) ? (u ^ 0x80000000u) : ~u;
    return __uint_as_float(v);
}

__device__ __forceinline__ void quat2mat(const float q[4], float R[3][3]) {
    float w = q[0], x = q[1], y = q[2], z = q[3];
    R[0][0] = 1.f - 2.f * (y * y + z * z);
    R[0][1] = 2.f * (x * y - w * z);
    R[0][2] = 2.f * (x * z + w * y);
    R[1][0] = 2.f * (x * y + w * z);
    R[1][1] = 1.f - 2.f * (x * x + z * z);
    R[1][2] = 2.f * (y * z - w * x);
    R[2][0] = 2.f * (x * z - w * y);
    R[2][1] = 2.f * (y * z + w * x);
    R[2][2] = 1.f - 2.f * (x * x + y * y);
}

// Kernel 1: grid=128 x 256.
//  - every thread: init one g_min entry, accumulate |p|^2 partial sum
//  - block 0 / warp 0: quaternion math -> g_A and cos_loss -> out[0]
__global__ __launch_bounds__(TPB) void prep_kernel(const float* __restrict__ pq,
                                                   const float* __restrict__ gq,
                                                   const float* __restrict__ points,
                                                   float* __restrict__ out) {
    const int tid  = threadIdx.x;
    const int gtid = blockIdx.x * TPB + tid;      // [0, 32768)

    // reset min table (graph replays reuse device globals)
    g_min[gtid] = 0xFFFFFFFFu;

    // |p|^2 partial sum (Sigma ysq == Sigma |p|^2 since rotation preserves norms)
    const int b = gtid >> 11;
    const int n = gtid & (NPTS - 1);
    const float* P = points + b * 3 * NPTS;
    float x = P[n], y = P[NPTS + n], z = P[2 * NPTS + n];
    float s = x * x + y * y + z * z;

    __shared__ float red[TPB / 32];
#pragma unroll
    for (int o = 16; o > 0; o >>= 1) s += __shfl_down_sync(0xFFFFFFFFu, s, o);
    if ((tid & 31) == 0) red[tid >> 5] = s;
    __syncthreads();
    if (tid < (TPB / 32)) {
        s = red[tid];
#pragma unroll
        for (int o = (TPB / 64); o > 0; o >>= 1) s += __shfl_down_sync(0xFFu, s, o);
        if (tid == 0) g_ssum[blockIdx.x] = s;
    }

    // quaternion work: block 0, warp 0
    if (blockIdx.x == 0 && tid < 32) {
        float cos_term = 0.f;
        if (tid < NB) {
            float p[4], g[4];
#pragma unroll
            for (int i = 0; i < 4; i++) { p[i] = pq[tid * 4 + i]; g[i] = gq[tid * 4 + i]; }
            float dot = 0.f, np2 = 0.f, ng2 = 0.f;
#pragma unroll
            for (int i = 0; i < 4; i++) {
                dot += p[i] * g[i]; np2 += p[i] * p[i]; ng2 += g[i] * g[i];
            }
            float np = sqrtf(np2), ng = sqrtf(ng2);
            cos_term = 1.f - dot / fmaxf(np * ng, 1e-8f);
            float ip = 1.f / fmaxf(np, 1e-8f);
            float ig = 1.f / fmaxf(ng, 1e-8f);
#pragma unroll
            for (int i = 0; i < 4; i++) { p[i] *= ip; g[i] *= ig; }
            float Rp[3][3], Rg[3][3];
            quat2mat(p, Rp);
            quat2mat(g, Rg);
            // A = Rp^T * Rg
#pragma unroll
            for (int i = 0; i < 3; i++)
#pragma unroll
                for (int j = 0; j < 3; j++) {
                    float a = 0.f;
#pragma unroll
                    for (int k = 0; k < 3; k++) a += Rp[k][i] * Rg[k][j];
                    g_A[tid * 9 + i * 3 + j] = a;
                }
        }
#pragma unroll
        for (int o = 16; o > 0; o >>= 1) cos_term += __shfl_down_sync(0xFFFFFFFFu, cos_term, o);
        if (tid == 0) out[0] = cos_term * (1.f / (float)NB);
    }
}

// Kernel 2: grid = 16 batches x 8 n-chunks. Each block handles 256 n-points
// against ALL 2048 m-points; each thread register-blocks MB=8 m-points.
// Partial mins combined across n-chunks via atomicMin (exact -> deterministic).
__global__ __launch_bounds__(TPB) void pair_kernel(const float* __restrict__ points) {
    // smA[j] = (r0[2j], r0[2j+1], r1[2j], r1[2j+1])
    // smB[j] = (r2[2j], r2[2j+1], s [2j], s [2j+1])
    __shared__ float4 smA[TPB / 2];
    __shared__ float4 smB[TPB / 2];

    const int b   = blockIdx.x >> 3;
    const int nc  = blockIdx.x & (NCHUNK - 1);
    const int tid = threadIdx.x;
    const float* __restrict__ P = points + b * 3 * NPTS;

    const float A00 = g_A[b * 9 + 0], A01 = g_A[b * 9 + 1], A02 = g_A[b * 9 + 2];
    const float A10 = g_A[b * 9 + 3], A11 = g_A[b * 9 + 4], A12 = g_A[b * 9 + 5];
    const float A20 = g_A[b * 9 + 6], A21 = g_A[b * 9 + 7], A22 = g_A[b * 9 + 8];

    // Phase 1: build r/s table for this block's 256 n-points (one n per thread).
    {
        int n = nc * TPB + tid;
        float x = P[n], y = P[NPTS + n], z = P[2 * NPTS + n];
        float r0 = A00 * x + A01 * y + A02 * z;
        float r1 = A10 * x + A11 * y + A12 * z;
        float r2 = A20 * x + A21 * y + A22 * z;
        float s  = x * x + y * y + z * z;
        float* fA = (float*)smA;
        float* fB = (float*)smB;
        int j = tid >> 1, h = tid & 1;
        fA[j * 4 + h]     = r0;
        fA[j * 4 + 2 + h] = r1;
        fB[j * 4 + h]     = r2;
        fB[j * 4 + 2 + h] = s;
    }
    __syncthreads();

    // Phase 2: each thread owns m = tid + k*256 for k in [0,8).
    ull u0[MB], u1[MB], u2[MB];
#pragma unroll
    for (int k = 0; k < MB; k++) {
        int m = k * TPB + tid;
        float mx = -2.f * P[m];
        float my = -2.f * P[NPTS + m];
        float mz = -2.f * P[2 * NPTS + m];
        u0[k] = pk2(mx, mx);
        u1[k] = pk2(my, my);
        u2[k] = pk2(mz, mz);
    }

    float mna[MB], mnb[MB];
#pragma unroll
    for (int k = 0; k < MB; k++) { mna[k] = INFINITY; mnb[k] = INFINITY; }

#pragma unroll 2
    for (int j = 0; j < TPB / 2; j++) {
        float4 a = smA[j];
        float4 q = smB[j];
        ull rp0 = pk2(a.x, a.y);
        ull rp1 = pk2(a.z, a.w);
        ull rp2 = pk2(q.x, q.y);
        ull sp  = pk2(q.z, q.w);
#pragma unroll
        for (int k = 0; k < MB; k++) {
            ull t = fma2(rp2, u2[k], sp);     // s - 2*r2*z   (2 n's at once)
            t = fma2(rp1, u1[k], t);          //   - 2*r1*y
            t = fma2(rp0, u0[k], t);          //   - 2*r0*x
            float fa, fb; upk2(t, fa, fb);
            mna[k] = fminf(mna[k], fa);
            mnb[k] = fminf(mnb[k], fb);
        }
    }

#pragma unroll
    for (int k = 0; k < MB; k++) {
        float v = fminf(mna[k], mnb[k]);
        atomicMin(&g_min[b * NPTS + k * TPB + tid], fenc(v));   // REDG, exact op
    }
}

// Kernel 3: single block, 1024 threads. pt_loss = (Sigma|p|^2 + Sigma min)/32768.
__global__ __launch_bounds__(1024) void finish_kernel(float* __restrict__ out) {
    const int tid = threadIdx.x;
    float acc = 0.f;
#pragma unroll
    for (int k = 0; k < (NB * NPTS) / 1024; k++)
        acc += fdec(g_min[tid + k * 1024]);
    if (tid < NBLK) acc += g_ssum[tid];

    __shared__ float red[32];
#pragma unroll
    for (int o = 16; o > 0; o >>= 1) acc += __shfl_down_sync(0xFFFFFFFFu, acc, o);
    if ((tid & 31) == 0) red[tid >> 5] = acc;
    __syncthreads();
    if (tid < 32) {
        acc = red[tid];
#pragma unroll
        for (int o = 16; o > 0; o >>= 1) acc += __shfl_down_sync(0xFFFFFFFFu, acc, o);
        if (tid == 0) {
            float pt = acc * (1.f / ((float)NB * (float)NPTS));
            if (isnan(pt)) pt = 0.f;
            out[1] = pt;
        }
    }
}

extern "C" void kernel_launch(void* const* d_in, const int* in_sizes, int n_in,
                              void* d_out, int out_size) {
    const float* pq  = (const float*)d_in[0];  // predquat (16,4)
    const float* gq  = (const float*)d_in[1];  // gtquat   (16,4)
    const float* pts = (const float*)d_in[2];  // points   (16,3,2048)
    float* out = (float*)d_out;                // [cos_loss, pt_loss]

    prep_kernel<<<NBLK, TPB>>>(pq, gq, pts, out);
    pair_kernel<<<NBLK, TPB>>>(pts);
    finish_kernel<<<1, 1024>>>(out);
}